// round 14
// baseline (speedup 1.0000x reference)
#include <cuda_runtime.h>
#include <cuda_fp16.h>
#include <stdint.h>
#include <math.h>

#define MROWS 8192
#define KDIM  2048
#define NDIM  2048
#define TLEN  4096
#define WSCALE 2048.0f
#define INVW   (1.0f / 2048.0f)

// fp16 operands (static device scratch)
__device__ __half g_A[(size_t)MROWS * KDIM];  // [m][k]  32 MB
__device__ __half g_B[(size_t)NDIM * KDIM];   // [n][k]   8 MB  (W^T * 2048)

// ---------------------------------------------------------------------------
// helpers
// ---------------------------------------------------------------------------
__device__ __forceinline__ uint32_t smem_u32(const void* p) {
    uint32_t a;
    asm("{ .reg .u64 t; cvta.to.shared.u64 t, %1; cvt.u32.u64 %0, t; }" : "=r"(a) : "l"(p));
    return a;
}
__device__ __forceinline__ uint32_t h2_u32(__half2 h) {
    uint32_t u;
    memcpy(&u, &h, 4);
    return u;
}
__device__ __forceinline__ void cp16(uint32_t dst, const void* src) {
    asm volatile("cp.async.cg.shared.global [%0], [%1], 16;" :: "r"(dst), "l"(src));
}
#define CP_COMMIT() asm volatile("cp.async.commit_group;" ::: "memory")
#define CP_WAIT1()  asm volatile("cp.async.wait_group 1;" ::: "memory")
#define CP_WAIT0()  asm volatile("cp.async.wait_group 0;" ::: "memory")

__device__ __forceinline__ void ldsm_x4(uint32_t a, uint32_t& r0, uint32_t& r1,
                                        uint32_t& r2, uint32_t& r3) {
    asm volatile("ldmatrix.sync.aligned.m8n8.x4.shared.b16 {%0,%1,%2,%3}, [%4];"
                 : "=r"(r0), "=r"(r1), "=r"(r2), "=r"(r3) : "r"(a));
}
__device__ __forceinline__ void mma_f16(float* d, const uint32_t* a, const uint32_t* b) {
    asm volatile(
        "mma.sync.aligned.m16n8k16.row.col.f32.f16.f16.f32 "
        "{%0,%1,%2,%3}, {%4,%5,%6,%7}, {%8,%9}, {%0,%1,%2,%3};"
        : "+f"(d[0]), "+f"(d[1]), "+f"(d[2]), "+f"(d[3])
        : "r"(a[0]), "r"(a[1]), "r"(a[2]), "r"(a[3]), "r"(b[0]), "r"(b[1]));
}

// ---------------------------------------------------------------------------
// Merged pre-pass: X->fp16 (32 elem/thread), W->fp16^T*2048, S_n tail copy.
// Blocks [0, XBLK): X ; [XBLK, XBLK+WBLK): W.
// ---------------------------------------------------------------------------
#define XBLK 2048                 // 2048 blk * 256 thr * 32 elem = 16.7M
#define WBLK 4096                 // (2048/32)^2

__global__ __launch_bounds__(256)
void convert_all(const float* __restrict__ X, const float* __restrict__ W,
                 const float* __restrict__ S_n, float* __restrict__ tail,
                 int ntail)
{
    if (blockIdx.x < XBLK) {
        int idx = blockIdx.x * 256 + threadIdx.x;     // 0..524287
        size_t e0 = (size_t)idx * 32;
#pragma unroll
        for (int u = 0; u < 4; ++u) {
            const float* src = X + e0 + u * 8;
            float4 v0 = *(const float4*)(src);
            float4 v1 = *(const float4*)(src + 4);
            uint32_t p0 = h2_u32(__floats2half2_rn(v0.x, v0.y));
            uint32_t p1 = h2_u32(__floats2half2_rn(v0.z, v0.w));
            uint32_t p2 = h2_u32(__floats2half2_rn(v1.x, v1.y));
            uint32_t p3 = h2_u32(__floats2half2_rn(v1.z, v1.w));
            *(uint4*)(g_A + e0 + u * 8) = make_uint4(p0, p1, p2, p3);
        }
        if (idx < ntail) tail[idx] = S_n[idx];        // S_n passthrough
    } else {
        __shared__ float tile[32][33];
        const int wb = blockIdx.x - XBLK;
        const int n0 = (wb & 63) * 32, k0 = (wb >> 6) * 32;
        const int tx = threadIdx.x & 31, ty = threadIdx.x >> 5;
#pragma unroll
        for (int r = 0; r < 4; ++r)
            tile[ty + r * 8][tx] = W[(size_t)(k0 + ty + r * 8) * NDIM + n0 + tx];
        __syncthreads();
#pragma unroll
        for (int r = 0; r < 4; ++r) {
            int n = n0 + ty + r * 8;
            g_B[(size_t)n * KDIM + k0 + tx] =
                __float2half_rn(tile[tx][ty + r * 8] * WSCALE);
        }
    }
}

// ---------------------------------------------------------------------------
// Main GEMM (certified R8 config): 128x128 tile/CTA (occ 2, 16 warps/SM),
// warp tile 64x32 (grid 2m x 4n), m16n8k16 fp16, KCH=64, 3-stage cp.async,
// SW128 swizzle, one __syncthreads per K-step.
// Fused RoPE/ReLU/bias/tanh/GroupNorm/transpose epilogue.
// ---------------------------------------------------------------------------
#define KCH      64
#define NIT      (KDIM / KCH)        // 32
#define STG      32768               // A 16KB + B 16KB per stage
#define AOFFS(s) ((s) * STG)
#define BOFFS(s) ((s) * STG + 16384)
#define EPST     132
#define DSMEM    98304               // 3 stages; epilogue (69,632B) reuses them

__global__ __launch_bounds__(256, 2)
void gemm_mma(const float* __restrict__ hh_b, const float* __restrict__ gw,
              const float* __restrict__ gb, float* __restrict__ out)
{
    extern __shared__ char smem[];
    const uint32_t sb = smem_u32(smem);
    const int tid  = threadIdx.x;
    const int wid  = tid >> 5, lane = tid & 31;
    const int wm   = wid >> 2, wn = wid & 3;      // warp grid 2(m) x 4(n)
    const int m0   = blockIdx.y * 128;
    const int n0   = blockIdx.x * 128;

    const __half* Ap = g_A + (size_t)m0 * KDIM;
    const __half* Bp = g_B + (size_t)n0 * KDIM;

    auto load_stage = [&](int it, int s) {
        const int kc = it * KCH;
#pragma unroll
        for (int u = 0; u < 4; ++u) {
            int ci = tid + u * 256;                // 0..1023
            int r = ci >> 3, c = ci & 7;
            uint32_t dof = (uint32_t)(r * 128 + ((c ^ (r & 7)) << 4));
            cp16(sb + AOFFS(s) + dof, Ap + (size_t)r * KDIM + kc + c * 8);
            cp16(sb + BOFFS(s) + dof, Bp + (size_t)r * KDIM + kc + c * 8);
        }
        CP_COMMIT();
    };

    float acc[4][4][4];
#pragma unroll
    for (int i = 0; i < 4; ++i)
#pragma unroll
        for (int j = 0; j < 4; ++j)
#pragma unroll
            for (int e = 0; e < 4; ++e) acc[i][j][e] = 0.f;

    load_stage(0, 0);
    load_stage(1, 1);

    // ldmatrix lane coords (SW128: chunk-col XOR (row&7))
    const int a_row = wm * 64 + (lane & 15);
    const int a_cb  = lane >> 4;
    const int b_row = wn * 32 + ((lane >> 4) << 3) + (lane & 7);
    const int b_cb  = (lane >> 3) & 1;

    for (int it = 0; it < NIT; ++it) {
        const int s = it % 3;
        if (it + 2 < NIT) { CP_WAIT1(); } else { CP_WAIT0(); }
        __syncthreads();                 // single barrier per K-step
        if (it + 2 < NIT) load_stage(it + 2, (it + 2) % 3);

        const uint32_t As = sb + AOFFS(s);
        const uint32_t Bs = sb + BOFFS(s);
#pragma unroll
        for (int kk = 0; kk < 4; ++kk) {
            uint32_t af[4][4], bf[4][2];
#pragma unroll
            for (int i = 0; i < 4; ++i) {
                int r = a_row + i * 16;
                int c = (kk * 2 + a_cb) ^ (r & 7);
                ldsm_x4(As + r * 128 + c * 16, af[i][0], af[i][1], af[i][2], af[i][3]);
            }
#pragma unroll
            for (int jj = 0; jj < 2; ++jj) {
                int r = b_row + jj * 16;
                int c = (kk * 2 + b_cb) ^ (r & 7);
                uint32_t r0, r1, r2, r3;
                ldsm_x4(Bs + r * 128 + c * 16, r0, r1, r2, r3);
                bf[jj * 2][0] = r0;     bf[jj * 2][1] = r1;
                bf[jj * 2 + 1][0] = r2; bf[jj * 2 + 1][1] = r3;
            }
#pragma unroll
            for (int i = 0; i < 4; ++i)
#pragma unroll
                for (int j = 0; j < 4; ++j)
                    mma_f16(acc[i][j], af[i], bf[j]);
        }
    }
    __syncthreads();   // stage buffers dead; smem becomes epilogue buffer

    // ---------------- fused epilogue (scale by 1/2048 for W prescale) -------
    float* ep  = (float*)smem;                     // [128 n][EPST m]
    float* mus = (float*)(smem + 128 * EPST * 4);  // [2][128]
    float* rss = mus + 256;

    const int bI = m0 >> 12;
    const int t0 = m0 & (TLEN - 1);
    const int qr = lane >> 2;
    const int qc = (lane & 3) * 2;

#pragma unroll
    for (int i = 0; i < 4; ++i) {
#pragma unroll
        for (int j = 0; j < 4; ++j) {
            const int coll = wn * 32 + j * 8 + qc;
            const int colg = n0 + coll;
            float c0 = acc[i][j][0] * INVW, c1 = acc[i][j][1] * INVW;
            float c2 = acc[i][j][2] * INVW, c3 = acc[i][j][3] * INVW;
            const int r0 = wm * 64 + i * 16 + qr;
            const int r1 = r0 + 8;
            if (colg < 64) {
                const float inv = powf(10000.0f, -(float)(colg >> 1) * (1.0f / 32.0f));
                float sn, cs;
                sincosf((float)((m0 + r0) & (TLEN - 1)) * inv, &sn, &cs);
                float e = c0, o = c1;
                c0 = e * cs - o * sn;  c1 = o * cs + e * sn;
                sincosf((float)((m0 + r1) & (TLEN - 1)) * inv, &sn, &cs);
                e = c2; o = c3;
                c2 = e * cs - o * sn;  c3 = o * cs + e * sn;
            }
            const float be = __ldg(hh_b + colg), bo = __ldg(hh_b + colg + 1);
            ep[coll * EPST + r0]       = tanhf(fmaxf(c0, 0.f) + be);
            ep[(coll + 1) * EPST + r0] = tanhf(fmaxf(c1, 0.f) + bo);
            ep[coll * EPST + r1]       = tanhf(fmaxf(c2, 0.f) + be);
            ep[(coll + 1) * EPST + r1] = tanhf(fmaxf(c3, 0.f) + bo);
        }
    }
    __syncthreads();

    {   // per-row GroupNorm stats over each 64-channel group
        const int m = tid & 127, g = tid >> 7;
        float s = 0.f;
#pragma unroll
        for (int c = 0; c < 64; ++c) s += ep[(g * 64 + c) * EPST + m];
        float mu = s * (1.f / 64.f);
        float ss = 0.f;
#pragma unroll
        for (int c = 0; c < 64; ++c) {
            float d = ep[(g * 64 + c) * EPST + m] - mu;
            ss = fmaf(d, d, ss);
        }
        mus[g * 128 + m] = mu;
        rss[g * 128 + m] = rsqrtf(ss * (1.f / 64.f) + 1e-5f);
    }
    __syncthreads();

    // normalize + transposed coalesced write
#pragma unroll
    for (int u = 0; u < 16; ++u) {
        int idx = tid + u * 256;
        int cn = idx >> 5, q = idx & 31;
        int g = cn >> 6;
        float w = __ldg(gw + n0 + cn), b = __ldg(gb + n0 + cn);
        float4 v = *(float4*)&ep[cn * EPST + q * 4];
        v.x = (v.x - mus[g * 128 + q * 4 + 0]) * rss[g * 128 + q * 4 + 0] * w + b;
        v.y = (v.y - mus[g * 128 + q * 4 + 1]) * rss[g * 128 + q * 4 + 1] * w + b;
        v.z = (v.z - mus[g * 128 + q * 4 + 2]) * rss[g * 128 + q * 4 + 2] * w + b;
        v.w = (v.w - mus[g * 128 + q * 4 + 3]) * rss[g * 128 + q * 4 + 3] * w + b;
        *(float4*)&out[(size_t)bI * TLEN * NDIM + (size_t)(n0 + cn) * TLEN
                       + t0 + q * 4] = v;
    }
}

// ---------------------------------------------------------------------------
extern "C" void kernel_launch(void* const* d_in, const int* in_sizes, int n_in,
                              void* d_out, int out_size)
{
    const float* X   = (const float*)d_in[0];
    const float* S_n = (const float*)d_in[1];
    const float* W_Q = (const float*)d_in[2];
    const float* hhb = (const float*)d_in[3];
    const float* gw  = (const float*)d_in[4];
    const float* gb  = (const float*)d_in[5];
    float* out = (float*)d_out;

    static bool attr_done = false;
    if (!attr_done) {
        cudaFuncSetAttribute(gemm_mma, cudaFuncAttributeMaxDynamicSharedMemorySize,
                             DSMEM);
        attr_done = true;
    }

    const long long OUT_ELEMS = (long long)2 * TLEN * NDIM;
    int ntail = (int)((long long)out_size - OUT_ELEMS);
    if (ntail < 0) ntail = 0;

    convert_all<<<XBLK + WBLK, 256>>>(X, W_Q, S_n, out + OUT_ELEMS, ntail);

    dim3 gg(NDIM / 128, MROWS / 128);    // (16, 64)
    gemm_mma<<<gg, 256, DSMEM>>>(hhb, gw, gb, out);
}

// round 15
// speedup vs baseline: 1.0422x; 1.0422x over previous
#include <cuda_runtime.h>
#include <cuda_fp16.h>
#include <stdint.h>
#include <math.h>

#define MROWS 8192
#define KDIM  2048
#define NDIM  2048
#define TLEN  4096
#define WSCALE 2048.0f
#define INVW   (1.0f / 2048.0f)

// fp16 operands (static device scratch)
__device__ __half g_A[(size_t)MROWS * KDIM];  // [m][k]  32 MB
__device__ __half g_B[(size_t)NDIM * KDIM];   // [n][k]   8 MB  (W^T * 2048)

// ---------------------------------------------------------------------------
// helpers
// ---------------------------------------------------------------------------
__device__ __forceinline__ uint32_t smem_u32(const void* p) {
    uint32_t a;
    asm("{ .reg .u64 t; cvta.to.shared.u64 t, %1; cvt.u32.u64 %0, t; }" : "=r"(a) : "l"(p));
    return a;
}
__device__ __forceinline__ uint32_t h2_u32(__half2 h) {
    uint32_t u;
    memcpy(&u, &h, 4);
    return u;
}
// hardware tanh (MUFU.TANH, sm_75+): ~1e-5 max rel error, 1 instruction
__device__ __forceinline__ float fast_tanh(float x) {
    float r;
    asm("tanh.approx.f32 %0, %1;" : "=f"(r) : "f"(x));
    return r;
}
__device__ __forceinline__ void cp16(uint32_t dst, const void* src) {
    asm volatile("cp.async.cg.shared.global [%0], [%1], 16;" :: "r"(dst), "l"(src));
}
#define CP_COMMIT() asm volatile("cp.async.commit_group;" ::: "memory")
#define CP_WAIT1()  asm volatile("cp.async.wait_group 1;" ::: "memory")
#define CP_WAIT0()  asm volatile("cp.async.wait_group 0;" ::: "memory")

__device__ __forceinline__ void ldsm_x4(uint32_t a, uint32_t& r0, uint32_t& r1,
                                        uint32_t& r2, uint32_t& r3) {
    asm volatile("ldmatrix.sync.aligned.m8n8.x4.shared.b16 {%0,%1,%2,%3}, [%4];"
                 : "=r"(r0), "=r"(r1), "=r"(r2), "=r"(r3) : "r"(a));
}
__device__ __forceinline__ void mma_f16(float* d, const uint32_t* a, const uint32_t* b) {
    asm volatile(
        "mma.sync.aligned.m16n8k16.row.col.f32.f16.f16.f32 "
        "{%0,%1,%2,%3}, {%4,%5,%6,%7}, {%8,%9}, {%0,%1,%2,%3};"
        : "+f"(d[0]), "+f"(d[1]), "+f"(d[2]), "+f"(d[3])
        : "r"(a[0]), "r"(a[1]), "r"(a[2]), "r"(a[3]), "r"(b[0]), "r"(b[1]));
}

// ---------------------------------------------------------------------------
// Merged pre-pass (R8 config): X->fp16 (8 elem/thread), W->fp16^T*2048,
// S_n tail copy. Blocks [0, XBLK): X ; [XBLK, XBLK+WBLK): W.
// ---------------------------------------------------------------------------
#define XBLK 8192                     // 8192 blk * 256 thr * 8 elem = 16.7M
#define WBLK 4096                     // (2048/32)^2

__global__ __launch_bounds__(256)
void convert_all(const float* __restrict__ X, const float* __restrict__ W,
                 const float* __restrict__ S_n, float* __restrict__ tail,
                 int ntail)
{
    if (blockIdx.x < XBLK) {
        int idx = blockIdx.x * 256 + threadIdx.x;
        size_t e0 = (size_t)idx * 8;
        const float* src = X + e0;
        float4 v0 = *(const float4*)(src);
        float4 v1 = *(const float4*)(src + 4);
        uint32_t p0 = h2_u32(__floats2half2_rn(v0.x, v0.y));
        uint32_t p1 = h2_u32(__floats2half2_rn(v0.z, v0.w));
        uint32_t p2 = h2_u32(__floats2half2_rn(v1.x, v1.y));
        uint32_t p3 = h2_u32(__floats2half2_rn(v1.z, v1.w));
        *(uint4*)(g_A + e0) = make_uint4(p0, p1, p2, p3);
        if (idx < ntail) tail[idx] = S_n[idx];
    } else {
        __shared__ float tile[32][33];
        const int wb = blockIdx.x - XBLK;
        const int n0 = (wb & 63) * 32, k0 = (wb >> 6) * 32;
        const int tx = threadIdx.x & 31, ty = threadIdx.x >> 5;
#pragma unroll
        for (int r = 0; r < 4; ++r)
            tile[ty + r * 8][tx] = W[(size_t)(k0 + ty + r * 8) * NDIM + n0 + tx];
        __syncthreads();
#pragma unroll
        for (int r = 0; r < 4; ++r) {
            int n = n0 + ty + r * 8;
            g_B[(size_t)n * KDIM + k0 + tx] =
                __float2half_rn(tile[tx][ty + r * 8] * WSCALE);
        }
    }
}

// ---------------------------------------------------------------------------
// Main GEMM (certified R8 config): 128x128 tile/CTA (occ 2, 16 warps/SM),
// warp tile 64x32 (grid 2m x 4n), m16n8k16 fp16, KCH=64, 3-stage cp.async,
// SW128 swizzle, one __syncthreads per K-step.
// Fused RoPE/ReLU/bias/tanh/GroupNorm/transpose epilogue (hw tanh).
// ---------------------------------------------------------------------------
#define KCH      64
#define NIT      (KDIM / KCH)        // 32
#define STG      32768               // A 16KB + B 16KB per stage
#define AOFFS(s) ((s) * STG)
#define BOFFS(s) ((s) * STG + 16384)
#define EPST     132
#define DSMEM    98304               // 3 stages; epilogue (69,632B) reuses them

__global__ __launch_bounds__(256, 2)
void gemm_mma(const float* __restrict__ hh_b, const float* __restrict__ gw,
              const float* __restrict__ gb, float* __restrict__ out)
{
    extern __shared__ char smem[];
    const uint32_t sb = smem_u32(smem);
    const int tid  = threadIdx.x;
    const int wid  = tid >> 5, lane = tid & 31;
    const int wm   = wid >> 2, wn = wid & 3;      // warp grid 2(m) x 4(n)
    const int m0   = blockIdx.y * 128;
    const int n0   = blockIdx.x * 128;

    const __half* Ap = g_A + (size_t)m0 * KDIM;
    const __half* Bp = g_B + (size_t)n0 * KDIM;

    auto load_stage = [&](int it, int s) {
        const int kc = it * KCH;
#pragma unroll
        for (int u = 0; u < 4; ++u) {
            int ci = tid + u * 256;                // 0..1023
            int r = ci >> 3, c = ci & 7;
            uint32_t dof = (uint32_t)(r * 128 + ((c ^ (r & 7)) << 4));
            cp16(sb + AOFFS(s) + dof, Ap + (size_t)r * KDIM + kc + c * 8);
            cp16(sb + BOFFS(s) + dof, Bp + (size_t)r * KDIM + kc + c * 8);
        }
        CP_COMMIT();
    };

    float acc[4][4][4];
#pragma unroll
    for (int i = 0; i < 4; ++i)
#pragma unroll
        for (int j = 0; j < 4; ++j)
#pragma unroll
            for (int e = 0; e < 4; ++e) acc[i][j][e] = 0.f;

    load_stage(0, 0);
    load_stage(1, 1);

    // ldmatrix lane coords (SW128: chunk-col XOR (row&7))
    const int a_row = wm * 64 + (lane & 15);
    const int a_cb  = lane >> 4;
    const int b_row = wn * 32 + ((lane >> 4) << 3) + (lane & 7);
    const int b_cb  = (lane >> 3) & 1;

    for (int it = 0; it < NIT; ++it) {
        const int s = it % 3;
        if (it + 2 < NIT) { CP_WAIT1(); } else { CP_WAIT0(); }
        __syncthreads();                 // single barrier per K-step
        if (it + 2 < NIT) load_stage(it + 2, (it + 2) % 3);

        const uint32_t As = sb + AOFFS(s);
        const uint32_t Bs = sb + BOFFS(s);
#pragma unroll
        for (int kk = 0; kk < 4; ++kk) {
            uint32_t af[4][4], bf[4][2];
#pragma unroll
            for (int i = 0; i < 4; ++i) {
                int r = a_row + i * 16;
                int c = (kk * 2 + a_cb) ^ (r & 7);
                ldsm_x4(As + r * 128 + c * 16, af[i][0], af[i][1], af[i][2], af[i][3]);
            }
#pragma unroll
            for (int jj = 0; jj < 2; ++jj) {
                int r = b_row + jj * 16;
                int c = (kk * 2 + b_cb) ^ (r & 7);
                uint32_t r0, r1, r2, r3;
                ldsm_x4(Bs + r * 128 + c * 16, r0, r1, r2, r3);
                bf[jj * 2][0] = r0;     bf[jj * 2][1] = r1;
                bf[jj * 2 + 1][0] = r2; bf[jj * 2 + 1][1] = r3;
            }
#pragma unroll
            for (int i = 0; i < 4; ++i)
#pragma unroll
                for (int j = 0; j < 4; ++j)
                    mma_f16(acc[i][j], af[i], bf[j]);
        }
    }
    __syncthreads();   // stage buffers dead; smem becomes epilogue buffer

    // ---------------- fused epilogue (scale by 1/2048 for W prescale) -------
    float* ep  = (float*)smem;                     // [128 n][EPST m]
    float* mus = (float*)(smem + 128 * EPST * 4);  // [2][128]
    float* rss = mus + 256;

    const int bI = m0 >> 12;
    const int t0 = m0 & (TLEN - 1);
    const int qr = lane >> 2;
    const int qc = (lane & 3) * 2;

#pragma unroll
    for (int i = 0; i < 4; ++i) {
#pragma unroll
        for (int j = 0; j < 4; ++j) {
            const int coll = wn * 32 + j * 8 + qc;
            const int colg = n0 + coll;
            float c0 = acc[i][j][0] * INVW, c1 = acc[i][j][1] * INVW;
            float c2 = acc[i][j][2] * INVW, c3 = acc[i][j][3] * INVW;
            const int r0 = wm * 64 + i * 16 + qr;
            const int r1 = r0 + 8;
            if (colg < 64) {
                const float inv = powf(10000.0f, -(float)(colg >> 1) * (1.0f / 32.0f));
                float sn, cs;
                sincosf((float)((m0 + r0) & (TLEN - 1)) * inv, &sn, &cs);
                float e = c0, o = c1;
                c0 = e * cs - o * sn;  c1 = o * cs + e * sn;
                sincosf((float)((m0 + r1) & (TLEN - 1)) * inv, &sn, &cs);
                e = c2; o = c3;
                c2 = e * cs - o * sn;  c3 = o * cs + e * sn;
            }
            const float be = __ldg(hh_b + colg), bo = __ldg(hh_b + colg + 1);
            ep[coll * EPST + r0]       = fast_tanh(fmaxf(c0, 0.f) + be);
            ep[(coll + 1) * EPST + r0] = fast_tanh(fmaxf(c1, 0.f) + bo);
            ep[coll * EPST + r1]       = fast_tanh(fmaxf(c2, 0.f) + be);
            ep[(coll + 1) * EPST + r1] = fast_tanh(fmaxf(c3, 0.f) + bo);
        }
    }
    __syncthreads();

    {   // per-row GroupNorm stats over each 64-channel group
        const int m = tid & 127, g = tid >> 7;
        float s = 0.f;
#pragma unroll
        for (int c = 0; c < 64; ++c) s += ep[(g * 64 + c) * EPST + m];
        float mu = s * (1.f / 64.f);
        float ss = 0.f;
#pragma unroll
        for (int c = 0; c < 64; ++c) {
            float d = ep[(g * 64 + c) * EPST + m] - mu;
            ss = fmaf(d, d, ss);
        }
        mus[g * 128 + m] = mu;
        rss[g * 128 + m] = rsqrtf(ss * (1.f / 64.f) + 1e-5f);
    }
    __syncthreads();

    // normalize + transposed coalesced write
#pragma unroll
    for (int u = 0; u < 16; ++u) {
        int idx = tid + u * 256;
        int cn = idx >> 5, q = idx & 31;
        int g = cn >> 6;
        float w = __ldg(gw + n0 + cn), b = __ldg(gb + n0 + cn);
        float4 v = *(float4*)&ep[cn * EPST + q * 4];
        v.x = (v.x - mus[g * 128 + q * 4 + 0]) * rss[g * 128 + q * 4 + 0] * w + b;
        v.y = (v.y - mus[g * 128 + q * 4 + 1]) * rss[g * 128 + q * 4 + 1] * w + b;
        v.z = (v.z - mus[g * 128 + q * 4 + 2]) * rss[g * 128 + q * 4 + 2] * w + b;
        v.w = (v.w - mus[g * 128 + q * 4 + 3]) * rss[g * 128 + q * 4 + 3] * w + b;
        *(float4*)&out[(size_t)bI * TLEN * NDIM + (size_t)(n0 + cn) * TLEN
                       + t0 + q * 4] = v;
    }
}

// ---------------------------------------------------------------------------
extern "C" void kernel_launch(void* const* d_in, const int* in_sizes, int n_in,
                              void* d_out, int out_size)
{
    const float* X   = (const float*)d_in[0];
    const float* S_n = (const float*)d_in[1];
    const float* W_Q = (const float*)d_in[2];
    const float* hhb = (const float*)d_in[3];
    const float* gw  = (const float*)d_in[4];
    const float* gb  = (const float*)d_in[5];
    float* out = (float*)d_out;

    static bool attr_done = false;
    if (!attr_done) {
        cudaFuncSetAttribute(gemm_mma, cudaFuncAttributeMaxDynamicSharedMemorySize,
                             DSMEM);
        attr_done = true;
    }

    const long long OUT_ELEMS = (long long)2 * TLEN * NDIM;
    int ntail = (int)((long long)out_size - OUT_ELEMS);
    if (ntail < 0) ntail = 0;

    convert_all<<<XBLK + WBLK, 256>>>(X, W_Q, S_n, out + OUT_ELEMS, ntail);

    dim3 gg(NDIM / 128, MROWS / 128);    // (16, 64)
    gemm_mma<<<gg, 256, DSMEM>>>(hhb, gw, gb, out);
}

// round 16
// speedup vs baseline: 1.0573x; 1.0145x over previous
#include <cuda_runtime.h>
#include <cuda_fp16.h>
#include <stdint.h>
#include <math.h>

#define MROWS 8192
#define KDIM  2048
#define NDIM  2048
#define TLEN  4096
#define WSCALE 2048.0f
#define INVW   (1.0f / 2048.0f)

// fp16 operands (static device scratch)
__device__ __half g_A[(size_t)MROWS * KDIM];  // [m][k]  32 MB
__device__ __half g_B[(size_t)NDIM * KDIM];   // [n][k]   8 MB  (W^T * 2048)
// RoPE cos/sin table: [t][freq] -> (cos, sin), 1 MB
__device__ float2 g_RC[(size_t)TLEN * 32];

// ---------------------------------------------------------------------------
// helpers
// ---------------------------------------------------------------------------
__device__ __forceinline__ uint32_t smem_u32(const void* p) {
    uint32_t a;
    asm("{ .reg .u64 t; cvta.to.shared.u64 t, %1; cvt.u32.u64 %0, t; }" : "=r"(a) : "l"(p));
    return a;
}
__device__ __forceinline__ uint32_t h2_u32(__half2 h) {
    uint32_t u;
    memcpy(&u, &h, 4);
    return u;
}
// hardware tanh (MUFU.TANH, sm_75+)
__device__ __forceinline__ float fast_tanh(float x) {
    float r;
    asm("tanh.approx.f32 %0, %1;" : "=f"(r) : "f"(x));
    return r;
}
__device__ __forceinline__ void cp16(uint32_t dst, const void* src) {
    asm volatile("cp.async.cg.shared.global [%0], [%1], 16;" :: "r"(dst), "l"(src));
}
#define CP_COMMIT() asm volatile("cp.async.commit_group;" ::: "memory")
#define CP_WAIT1()  asm volatile("cp.async.wait_group 1;" ::: "memory")
#define CP_WAIT0()  asm volatile("cp.async.wait_group 0;" ::: "memory")

__device__ __forceinline__ void ldsm_x4(uint32_t a, uint32_t& r0, uint32_t& r1,
                                        uint32_t& r2, uint32_t& r3) {
    asm volatile("ldmatrix.sync.aligned.m8n8.x4.shared.b16 {%0,%1,%2,%3}, [%4];"
                 : "=r"(r0), "=r"(r1), "=r"(r2), "=r"(r3) : "r"(a));
}
__device__ __forceinline__ void mma_f16(float* d, const uint32_t* a, const uint32_t* b) {
    asm volatile(
        "mma.sync.aligned.m16n8k16.row.col.f32.f16.f16.f32 "
        "{%0,%1,%2,%3}, {%4,%5,%6,%7}, {%8,%9}, {%0,%1,%2,%3};"
        : "+f"(d[0]), "+f"(d[1]), "+f"(d[2]), "+f"(d[3])
        : "r"(a[0]), "r"(a[1]), "r"(a[2]), "r"(a[3]), "r"(b[0]), "r"(b[1]));
}

// ---------------------------------------------------------------------------
// Merged pre-pass: X->fp16 (8 elem/thread), W->fp16^T*2048, RoPE table,
// S_n tail copy. Blocks: [0,XBLK) X ; [XBLK,XBLK+WBLK) W ; rest RoPE table.
// ---------------------------------------------------------------------------
#define XBLK 8192                     // 8192 blk * 256 thr * 8 elem = 16.7M
#define WBLK 4096                     // (2048/32)^2
#define RBLK 512                      // 512 blk * 256 thr = TLEN*32 entries

__global__ __launch_bounds__(256)
void convert_all(const float* __restrict__ X, const float* __restrict__ W,
                 const float* __restrict__ S_n, float* __restrict__ tail,
                 int ntail)
{
    if (blockIdx.x < XBLK) {
        int idx = blockIdx.x * 256 + threadIdx.x;
        size_t e0 = (size_t)idx * 8;
        const float* src = X + e0;
        float4 v0 = *(const float4*)(src);
        float4 v1 = *(const float4*)(src + 4);
        uint32_t p0 = h2_u32(__floats2half2_rn(v0.x, v0.y));
        uint32_t p1 = h2_u32(__floats2half2_rn(v0.z, v0.w));
        uint32_t p2 = h2_u32(__floats2half2_rn(v1.x, v1.y));
        uint32_t p3 = h2_u32(__floats2half2_rn(v1.z, v1.w));
        *(uint4*)(g_A + e0) = make_uint4(p0, p1, p2, p3);
        if (idx < ntail) tail[idx] = S_n[idx];
    } else if (blockIdx.x < XBLK + WBLK) {
        __shared__ float tile[32][33];
        const int wb = blockIdx.x - XBLK;
        const int n0 = (wb & 63) * 32, k0 = (wb >> 6) * 32;
        const int tx = threadIdx.x & 31, ty = threadIdx.x >> 5;
#pragma unroll
        for (int r = 0; r < 4; ++r)
            tile[ty + r * 8][tx] = W[(size_t)(k0 + ty + r * 8) * NDIM + n0 + tx];
        __syncthreads();
#pragma unroll
        for (int r = 0; r < 4; ++r) {
            int n = n0 + ty + r * 8;
            g_B[(size_t)n * KDIM + k0 + tx] =
                __float2half_rn(tile[tx][ty + r * 8] * WSCALE);
        }
    } else {
        // RoPE cos/sin table: idx -> t = idx>>5, f = idx&31
        int idx = (blockIdx.x - XBLK - WBLK) * 256 + threadIdx.x;
        int t = idx >> 5, f = idx & 31;
        float inv = powf(10000.0f, -(float)f * (1.0f / 32.0f));
        float sn, cs;
        sincosf((float)t * inv, &sn, &cs);
        g_RC[idx] = make_float2(cs, sn);
    }
}

// ---------------------------------------------------------------------------
// Main GEMM (certified R8 config): 128x128 tile/CTA (occ 2, 16 warps/SM),
// warp tile 64x32 (grid 2m x 4n), m16n8k16 fp16, KCH=64, 3-stage cp.async,
// SW128 swizzle, one __syncthreads per K-step, tight wait_group schedule.
// Fused RoPE(table)/ReLU/bias/hw-tanh/GroupNorm/transpose epilogue.
// ---------------------------------------------------------------------------
#define KCH      64
#define NIT      (KDIM / KCH)        // 32
#define STG      32768               // A 16KB + B 16KB per stage
#define AOFFS(s) ((s) * STG)
#define BOFFS(s) ((s) * STG + 16384)
#define EPST     132
#define DSMEM    98304               // 3 stages; epilogue (69,632B) reuses them

__global__ __launch_bounds__(256, 2)
void gemm_mma(const float* __restrict__ hh_b, const float* __restrict__ gw,
              const float* __restrict__ gb, float* __restrict__ out)
{
    extern __shared__ char smem[];
    const uint32_t sb = smem_u32(smem);
    const int tid  = threadIdx.x;
    const int wid  = tid >> 5, lane = tid & 31;
    const int wm   = wid >> 2, wn = wid & 3;      // warp grid 2(m) x 4(n)
    const int m0   = blockIdx.y * 128;
    const int n0   = blockIdx.x * 128;

    const __half* Ap = g_A + (size_t)m0 * KDIM;
    const __half* Bp = g_B + (size_t)n0 * KDIM;

    auto load_stage = [&](int it, int s) {
        const int kc = it * KCH;
#pragma unroll
        for (int u = 0; u < 4; ++u) {
            int ci = tid + u * 256;                // 0..1023
            int r = ci >> 3, c = ci & 7;
            uint32_t dof = (uint32_t)(r * 128 + ((c ^ (r & 7)) << 4));
            cp16(sb + AOFFS(s) + dof, Ap + (size_t)r * KDIM + kc + c * 8);
            cp16(sb + BOFFS(s) + dof, Bp + (size_t)r * KDIM + kc + c * 8);
        }
        CP_COMMIT();
    };

    float acc[4][4][4];
#pragma unroll
    for (int i = 0; i < 4; ++i)
#pragma unroll
        for (int j = 0; j < 4; ++j)
#pragma unroll
            for (int e = 0; e < 4; ++e) acc[i][j][e] = 0.f;

    load_stage(0, 0);
    load_stage(1, 1);

    // ldmatrix lane coords (SW128: chunk-col XOR (row&7))
    const int a_row = wm * 64 + (lane & 15);
    const int a_cb  = lane >> 4;
    const int b_row = wn * 32 + ((lane >> 4) << 3) + (lane & 7);
    const int b_cb  = (lane >> 3) & 1;

    for (int it = 0; it < NIT; ++it) {
        const int s = it % 3;
        if (it + 1 < NIT) { CP_WAIT1(); } else { CP_WAIT0(); }
        __syncthreads();                 // single barrier per K-step
        if (it + 2 < NIT) load_stage(it + 2, (it + 2) % 3);

        const uint32_t As = sb + AOFFS(s);
        const uint32_t Bs = sb + BOFFS(s);
#pragma unroll
        for (int kk = 0; kk < 4; ++kk) {
            uint32_t af[4][4], bf[4][2];
#pragma unroll
            for (int i = 0; i < 4; ++i) {
                int r = a_row + i * 16;
                int c = (kk * 2 + a_cb) ^ (r & 7);
                ldsm_x4(As + r * 128 + c * 16, af[i][0], af[i][1], af[i][2], af[i][3]);
            }
#pragma unroll
            for (int jj = 0; jj < 2; ++jj) {
                int r = b_row + jj * 16;
                int c = (kk * 2 + b_cb) ^ (r & 7);
                uint32_t r0, r1, r2, r3;
                ldsm_x4(Bs + r * 128 + c * 16, r0, r1, r2, r3);
                bf[jj * 2][0] = r0;     bf[jj * 2][1] = r1;
                bf[jj * 2 + 1][0] = r2; bf[jj * 2 + 1][1] = r3;
            }
#pragma unroll
            for (int i = 0; i < 4; ++i)
#pragma unroll
                for (int j = 0; j < 4; ++j)
                    mma_f16(acc[i][j], af[i], bf[j]);
        }
    }
    __syncthreads();   // stage buffers dead; smem becomes epilogue buffer

    // ---------------- fused epilogue (scale by 1/2048 for W prescale) -------
    float* ep  = (float*)smem;                     // [128 n][EPST m]
    float* mus = (float*)(smem + 128 * EPST * 4);  // [2][128]
    float* rss = mus + 256;

    const int bI = m0 >> 12;
    const int t0 = m0 & (TLEN - 1);
    const int qr = lane >> 2;
    const int qc = (lane & 3) * 2;

#pragma unroll
    for (int i = 0; i < 4; ++i) {
#pragma unroll
        for (int j = 0; j < 4; ++j) {
            const int coll = wn * 32 + j * 8 + qc;
            const int colg = n0 + coll;
            float c0 = acc[i][j][0] * INVW, c1 = acc[i][j][1] * INVW;
            float c2 = acc[i][j][2] * INVW, c3 = acc[i][j][3] * INVW;
            const int r0 = wm * 64 + i * 16 + qr;
            const int r1 = r0 + 8;
            if (colg < 64) {                        // RoPE via precomputed table
                const int f = colg >> 1;
                float2 cs0 = __ldg(&g_RC[(size_t)((m0 + r0) & (TLEN - 1)) * 32 + f]);
                float2 cs1 = __ldg(&g_RC[(size_t)((m0 + r1) & (TLEN - 1)) * 32 + f]);
                float e = c0, o = c1;
                c0 = e * cs0.x - o * cs0.y;  c1 = o * cs0.x + e * cs0.y;
                e = c2; o = c3;
                c2 = e * cs1.x - o * cs1.y;  c3 = o * cs1.x + e * cs1.y;
            }
            const float be = __ldg(hh_b + colg), bo = __ldg(hh_b + colg + 1);
            ep[coll * EPST + r0]       = fast_tanh(fmaxf(c0, 0.f) + be);
            ep[(coll + 1) * EPST + r0] = fast_tanh(fmaxf(c1, 0.f) + bo);
            ep[coll * EPST + r1]       = fast_tanh(fmaxf(c2, 0.f) + be);
            ep[(coll + 1) * EPST + r1] = fast_tanh(fmaxf(c3, 0.f) + bo);
        }
    }
    __syncthreads();

    {   // per-row GroupNorm stats over each 64-channel group
        const int m = tid & 127, g = tid >> 7;
        float s = 0.f;
#pragma unroll
        for (int c = 0; c < 64; ++c) s += ep[(g * 64 + c) * EPST + m];
        float mu = s * (1.f / 64.f);
        float ss = 0.f;
#pragma unroll
        for (int c = 0; c < 64; ++c) {
            float d = ep[(g * 64 + c) * EPST + m] - mu;
            ss = fmaf(d, d, ss);
        }
        mus[g * 128 + m] = mu;
        rss[g * 128 + m] = rsqrtf(ss * (1.f / 64.f) + 1e-5f);
    }
    __syncthreads();

    // normalize + transposed coalesced write
#pragma unroll
    for (int u = 0; u < 16; ++u) {
        int idx = tid + u * 256;
        int cn = idx >> 5, q = idx & 31;
        int g = cn >> 6;
        float w = __ldg(gw + n0 + cn), b = __ldg(gb + n0 + cn);
        float4 v = *(float4*)&ep[cn * EPST + q * 4];
        v.x = (v.x - mus[g * 128 + q * 4 + 0]) * rss[g * 128 + q * 4 + 0] * w + b;
        v.y = (v.y - mus[g * 128 + q * 4 + 1]) * rss[g * 128 + q * 4 + 1] * w + b;
        v.z = (v.z - mus[g * 128 + q * 4 + 2]) * rss[g * 128 + q * 4 + 2] * w + b;
        v.w = (v.w - mus[g * 128 + q * 4 + 3]) * rss[g * 128 + q * 4 + 3] * w + b;
        *(float4*)&out[(size_t)bI * TLEN * NDIM + (size_t)(n0 + cn) * TLEN
                       + t0 + q * 4] = v;
    }
}

// ---------------------------------------------------------------------------
extern "C" void kernel_launch(void* const* d_in, const int* in_sizes, int n_in,
                              void* d_out, int out_size)
{
    const float* X   = (const float*)d_in[0];
    const float* S_n = (const float*)d_in[1];
    const float* W_Q = (const float*)d_in[2];
    const float* hhb = (const float*)d_in[3];
    const float* gw  = (const float*)d_in[4];
    const float* gb  = (const float*)d_in[5];
    float* out = (float*)d_out;

    static bool attr_done = false;
    if (!attr_done) {
        cudaFuncSetAttribute(gemm_mma, cudaFuncAttributeMaxDynamicSharedMemorySize,
                             DSMEM);
        attr_done = true;
    }

    const long long OUT_ELEMS = (long long)2 * TLEN * NDIM;
    int ntail = (int)((long long)out_size - OUT_ELEMS);
    if (ntail < 0) ntail = 0;

    convert_all<<<XBLK + WBLK + RBLK, 256>>>(X, W_Q, S_n, out + OUT_ELEMS, ntail);

    dim3 gg(NDIM / 128, MROWS / 128);    // (16, 64)
    gemm_mma<<<gg, 256, DSMEM>>>(hhb, gw, gb, out);
}